// round 1
// baseline (speedup 1.0000x reference)
#include <cuda_runtime.h>
#include <math.h>

#define DIN   128
#define DOUT  128
#define NB    2048
#define NU    20000
#define NMC   4
#define EPB   32     // edges per node (E/B = 65536/2048)
#define RES   0.9f

// Scratch (static __device__ arrays per harness rules)
__device__ float g_embed_v[NU * DOUT];        // [20000,128]
__device__ float g_agg_all[NB * 3 * DOUT];    // [2048, 384] = self_agg | K0 | Q0
__device__ float g_ff_all [NB * 3 * DOUT];    // [2048, 384] = self_ff  | K1 | Q1

// ---------------------------------------------------------------------------
// Gather-GEMM: out[r, blockIdx.y*128 + n] = sum_k table[idx[r],k] * W_y[k,n]
// Tile: 64 rows x 128 cols, full K=128. 256 threads, 4x8 micro-tile/thread.
// A staged in smem as [row][k] with row stride 132 floats:
//   - STS.128 writes land in a contiguous 512B window per warp (132*4=528=33*16)
//   - per-k scalar LDS of A is a 2-address broadcast within a warp
// ---------------------------------------------------------------------------
__global__ __launch_bounds__(256) void gemm_gather_kernel(
    const float* __restrict__ table, const int* __restrict__ idx, int M,
    const float* __restrict__ W0, const float* __restrict__ W1,
    const float* __restrict__ W2,
    float* __restrict__ out, int ldout)
{
    extern __shared__ float smem[];
    float* Bs = smem;                 // [128][128] row-major (k, n)
    float* As = smem + 128 * 128;     // [64][132]  (row, k), padded stride

    const float* W = (blockIdx.y == 0) ? W0 : (blockIdx.y == 1 ? W1 : W2);
    const int row0 = blockIdx.x * 64;
    const int t = threadIdx.x;

    // Load W tile: 16384 floats = 4096 float4
    {
        const float4* Wv = (const float4*)W;
        float4* Bv = (float4*)Bs;
        #pragma unroll
        for (int i = 0; i < 16; i++) Bv[t + i * 256] = Wv[t + i * 256];
    }
    // Load gathered A: 64 rows x 32 float4; coalesced per gathered row
    #pragma unroll
    for (int it = 0; it < 8; it++) {
        int i = t + it * 256;
        int row = i >> 5;
        int kq  = i & 31;
        int gr  = row0 + row;
        float4 v = make_float4(0.f, 0.f, 0.f, 0.f);
        if (gr < M) v = *(const float4*)(table + idx[gr] * DIN + kq * 4);
        *(float4*)(As + row * 132 + kq * 4) = v;
    }
    __syncthreads();

    const int cg = t & 15;   // cols cg*8 .. cg*8+7
    const int rg = t >> 4;   // rows rg*4 .. rg*4+3
    float acc[4][8];
    #pragma unroll
    for (int i = 0; i < 4; i++)
        #pragma unroll
        for (int j = 0; j < 8; j++) acc[i][j] = 0.f;

    const float* arow = As + rg * 4 * 132;
    const float* bcol = Bs + cg * 8;

    #pragma unroll 4
    for (int k = 0; k < 128; k++) {
        float av[4];
        av[0] = arow[0 * 132 + k];
        av[1] = arow[1 * 132 + k];
        av[2] = arow[2 * 132 + k];
        av[3] = arow[3 * 132 + k];
        float4 b0 = *(const float4*)(bcol + k * 128);
        float4 b1 = *(const float4*)(bcol + k * 128 + 4);
        float bv[8] = {b0.x, b0.y, b0.z, b0.w, b1.x, b1.y, b1.z, b1.w};
        #pragma unroll
        for (int i = 0; i < 4; i++)
            #pragma unroll
            for (int j = 0; j < 8; j++) acc[i][j] += av[i] * bv[j];
    }

    const int ncol0 = blockIdx.y * 128 + cg * 8;
    #pragma unroll
    for (int i = 0; i < 4; i++) {
        int gr = row0 + rg * 4 + i;
        if (gr < M) {
            float* op = out + gr * ldout + ncol0;
            *(float4*)(op)     = make_float4(acc[i][0], acc[i][1], acc[i][2], acc[i][3]);
            *(float4*)(op + 4) = make_float4(acc[i][4], acc[i][5], acc[i][6], acc[i][7]);
        }
    }
}

// ---------------------------------------------------------------------------
// Block-wide sum over 128 threads (broadcast result to all threads)
// ---------------------------------------------------------------------------
__device__ __forceinline__ float blockSum(float v, float* red)
{
    const int lane = threadIdx.x & 31;
    const int w    = threadIdx.x >> 5;
    #pragma unroll
    for (int o = 16; o > 0; o >>= 1) v += __shfl_xor_sync(0xffffffffu, v, o);
    if (lane == 0) red[w] = v;
    __syncthreads();
    v = red[0] + red[1] + red[2] + red[3];
    __syncthreads();
    return v;
}

// ---------------------------------------------------------------------------
// Finalize: per-node edge dedup+mean aggregation, persona softmax, highway
// attention, ELU. One block (128 threads) per node.
// ---------------------------------------------------------------------------
__global__ __launch_bounds__(128) void finalize_kernel(
    const int* __restrict__ layer_idx, const int* __restrict__ col_idx,
    const float* __restrict__ mu_w, float* __restrict__ out)
{
    const int b = blockIdx.x;
    const int d = threadIdx.x;

    __shared__ int   s_lay[EPB], s_col[EPB], s_vm[EPB];
    __shared__ float s_cnt[NMC];
    __shared__ float red[4];

    if (d < EPB) {
        s_lay[d] = layer_idx[b * EPB + d];
        s_col[d] = col_idx[b * EPB + d];
    }
    if (d < NMC) s_cnt[d] = 0.f;
    __syncthreads();

    // Dedup: keep first occurrence of each (layer, col) pair (set semantics)
    if (d < EPB) {
        int m = s_lay[d], c = s_col[d];
        bool val = true;
        for (int j = 0; j < d; j++)
            if (s_lay[j] == m && s_col[j] == c) { val = false; break; }
        s_vm[d] = val ? m : -1;
        if (val) atomicAdd(&s_cnt[m], 1.f);
    }
    __syncthreads();

    // neigh[m][d]: mean over distinct neighbors per layer (uniform branches)
    float nb4[NMC] = {0.f, 0.f, 0.f, 0.f};
    #pragma unroll
    for (int e = 0; e < EPB; e++) {
        int m = s_vm[e];
        if (m >= 0) {
            float v = g_embed_v[s_col[e] * DOUT + d];
            if      (m == 0) nb4[0] += v;
            else if (m == 1) nb4[1] += v;
            else if (m == 2) nb4[2] += v;
            else             nb4[3] += v;
        }
    }
    #pragma unroll
    for (int m = 0; m < NMC; m++)
        nb4[m] = (s_cnt[m] > 0.f) ? nb4[m] / s_cnt[m] : 0.f;

    const float* ar = g_agg_all + b * (3 * DOUT);
    const float* fr = g_ff_all  + b * (3 * DOUT);
    float sa  = ar[d], k0 = ar[DOUT + d], q0 = ar[2 * DOUT + d];
    float sff = fr[d], k1 = fr[DOUT + d], q1 = fr[2 * DOUT + d];
    float mu0 = mu_w[d], mu1 = mu_w[DOUT + d];

    // persona coefficients: normalized concat [sa, neigh_m] dotted with mu_w
    float r_sa2  = blockSum(sa * sa,  red);
    float r_samu = blockSum(sa * mu0, red);
    float logit[NMC];
    #pragma unroll
    for (int m = 0; m < NMC; m++) {
        float r_n2  = blockSum(nb4[m] * nb4[m], red);
        float r_nmu = blockSum(nb4[m] * mu1,    red);
        logit[m] = (r_samu + r_nmu) / fmaxf(sqrtf(r_sa2 + r_n2), 1e-12f);
    }
    float mx = fmaxf(fmaxf(logit[0], logit[1]), fmaxf(logit[2], logit[3]));
    float ex[NMC], es = 0.f;
    #pragma unroll
    for (int m = 0; m < NMC; m++) { ex[m] = expf(logit[m] - mx); es += ex[m]; }
    float nsum = 0.f;
    #pragma unroll
    for (int m = 0; m < NMC; m++) nsum += (ex[m] / es) * nb4[m];

    float va = 0.5f * (sa + nsum);   // updated self_agg (= V[:,0])

    // 2x2 highway attention: S[i][j] = K_i . Q_j / DOUT, softmax over j
    float s00 = blockSum(k0 * q0, red) * (1.f / 128.f);
    float s01 = blockSum(k0 * q1, red) * (1.f / 128.f);
    float s10 = blockSum(k1 * q0, red) * (1.f / 128.f);
    float s11 = blockSum(k1 * q1, red) * (1.f / 128.f);
    float m0 = fmaxf(s00, s01), m1 = fmaxf(s10, s11);
    float e00 = expf(s00 - m0), e01 = expf(s01 - m0);
    float e10 = expf(s10 - m1), e11 = expf(s11 - m1);
    float new0 = (e00 * va + e01 * sff) / (e00 + e01);
    float new1 = (e10 * va + e11 * sff) / (e10 + e11);

    float o0 = RES * va  + (1.f - RES) * new0;
    float o1 = RES * sff + (1.f - RES) * new1;
    o0 = (o0 > 0.f) ? o0 : expm1f(o0);
    o1 = (o1 > 0.f) ? o1 : expm1f(o1);

    out[b * DOUT + d]             = o0;   // elu(self_agg)
    out[NB * DOUT + b * DOUT + d] = o1;   // elu(self_ff)
}

// ---------------------------------------------------------------------------
extern "C" void kernel_launch(void* const* d_in, const int* in_sizes, int n_in,
                              void* d_out, int out_size)
{
    const int*   nodes      = (const int*)  d_in[0];
    const int*   unique_ids = (const int*)  d_in[1];
    // d_in[2] = row_idx: structurally repeat(arange(B), 32) — implicit
    const int*   layer_idx  = (const int*)  d_in[3];
    const int*   col_idx    = (const int*)  d_in[4];
    const float* agg_table  = (const float*)d_in[5];
    const float* ff_table   = (const float*)d_in[6];
    const float* Wv_agg     = (const float*)d_in[7];
    const float* Wv_ff      = (const float*)d_in[8];
    const float* Wk         = (const float*)d_in[9];
    const float* Wq         = (const float*)d_in[10];
    const float* mu_w       = (const float*)d_in[11];
    float* out = (float*)d_out;

    float *embed_v, *agg_all, *ff_all;
    cudaGetSymbolAddress((void**)&embed_v, g_embed_v);
    cudaGetSymbolAddress((void**)&agg_all, g_agg_all);
    cudaGetSymbolAddress((void**)&ff_all,  g_ff_all);

    const int smem_bytes = (128 * 128 + 64 * 132) * sizeof(float);  // 99328
    cudaFuncSetAttribute(gemm_gather_kernel,
                         cudaFuncAttributeMaxDynamicSharedMemorySize, smem_bytes);

    // GEMM3: embed_agg_v = agg_table[unique_ids] @ Wv_agg   [20000,128]
    dim3 g3((NU + 63) / 64, 1);
    gemm_gather_kernel<<<g3, 256, smem_bytes>>>(
        agg_table, unique_ids, NU, Wv_agg, Wv_agg, Wv_agg, embed_v, DOUT);

    // GEMM1: agg_all = agg_table[nodes] @ [Wv_agg | Wk | Wq]  [2048,384]
    dim3 g1(NB / 64, 3);
    gemm_gather_kernel<<<g1, 256, smem_bytes>>>(
        agg_table, nodes, NB, Wv_agg, Wk, Wq, agg_all, 3 * DOUT);

    // GEMM2: ff_all = ff_table[nodes] @ [Wv_ff | Wk | Wq]     [2048,384]
    gemm_gather_kernel<<<g1, 256, smem_bytes>>>(
        ff_table, nodes, NB, Wv_ff, Wk, Wq, ff_all, 3 * DOUT);

    // Edge aggregation + epilogue
    finalize_kernel<<<NB, 128>>>(layer_idx, col_idx, mu_w, out);
}

// round 2
// speedup vs baseline: 2.1421x; 2.1421x over previous
#include <cuda_runtime.h>
#include <math.h>

#define DIN   128
#define DOUT  128
#define NB    2048
#define NU    20000
#define NMC   4
#define EPB   32
#define RES   0.9f

#define NB3   79            // ceil(20000/256) blocks for GEMM3
#define LDA   132           // A smem row stride (words) -> conflict-free frag loads
#define LDW   132           // per (kk,jp) group stride (words) in Wfrag

// Scratch
__device__ float g_embed_v[NU * DOUT];        // [20000,128]
__device__ float g_agg_all[NB * 3 * DOUT];    // [2048,384] = self_agg | K0 | Q0
__device__ float g_ff_all [NB * 3 * DOUT];    // [2048,384] = self_ff  | K1 | Q1

__device__ __forceinline__ unsigned f2tf32(float f) {
    unsigned u;
    asm("cvt.rna.tf32.f32 %0, %1;" : "=r"(u) : "f"(f));
    return u;
}

__device__ __forceinline__ void mma_tf32(float* c, const unsigned* a, unsigned b0, unsigned b1) {
    asm volatile(
        "mma.sync.aligned.m16n8k8.row.col.f32.tf32.tf32.f32 "
        "{%0,%1,%2,%3}, {%4,%5,%6,%7}, {%8,%9}, {%0,%1,%2,%3};\n"
        : "+f"(c[0]), "+f"(c[1]), "+f"(c[2]), "+f"(c[3])
        : "r"(a[0]), "r"(a[1]), "r"(a[2]), "r"(a[3]), "r"(b0), "r"(b1));
}

// ---------------------------------------------------------------------------
// Merged gather-GEMM (tf32 tensor cores).
// Block: m256 x n128, K=128 (whole). 256 threads = 8 warps, each warp m32.
// Jobs:  bx<79:        embed_v  = agg_table[unique_ids] @ Wv_agg
//        79<=bx<103:   agg_all  = agg_table[nodes] @ {Wv_agg|Wk|Wq}
//        103<=bx<127:  ff_all   = ff_table[nodes]  @ {Wv_ff |Wk|Wq}
// ---------------------------------------------------------------------------
__global__ __launch_bounds__(256, 1) void gemm_tc_kernel(
    const float* __restrict__ agg_table, const float* __restrict__ ff_table,
    const int* __restrict__ unique_ids,  const int* __restrict__ nodes,
    const float* __restrict__ Wv_agg, const float* __restrict__ Wv_ff,
    const float* __restrict__ Wk,     const float* __restrict__ Wq,
    float* __restrict__ embed_v, float* __restrict__ agg_all, float* __restrict__ ff_all)
{
    extern __shared__ unsigned smem[];
    unsigned* As = smem;                    // [256][LDA] tf32 bits
    unsigned* Wf = smem + 256 * LDA;        // [16*8][LDW] fragment-major W

    // ---- job decode ----
    const float* table; const int* idx; const float* W; float* out;
    int M, ldout, col0, row0;
    int bx = blockIdx.x;
    if (bx < NB3) {
        table = agg_table; idx = unique_ids; W = Wv_agg; out = g_embed_v;
        M = NU; ldout = DOUT; col0 = 0; row0 = bx * 256;
    } else {
        int b = bx - NB3;
        int grp = b / 24;            // 0: agg, 1: ff
        int b2 = b % 24;
        int wsel = b2 / 8, mb = b2 % 8;
        table = grp ? ff_table : agg_table;
        idx = nodes;
        W = (wsel == 0) ? (grp ? Wv_ff : Wv_agg) : (wsel == 1 ? Wk : Wq);
        out = grp ? g_ff_all : g_agg_all;
        M = NB; ldout = 3 * DOUT; col0 = wsel * 128; row0 = mb * 256;
    }

    const int t = threadIdx.x;
    const int lane = t & 31;
    const int warp = t >> 5;
    const int g  = lane >> 2;   // 0..7
    const int tg = lane & 3;    // 0..3

    __shared__ int s_idx[256];
    {
        int r = row0 + t;
        s_idx[t] = (r < M) ? idx[r] : 0;
    }

    // ---- stage W in fragment-major layout (coalesced float4 loads) ----
    // slot(row,col): kk=row>>3, tg'=row&3, half=(row>>3? no:(row&7)>>2), ...
    {
        #pragma unroll
        for (int i = 0; i < 16; i++) {
            int e = t + i * 256;          // float4 index: 4096 total
            int row = e >> 5;             // 0..127
            int col = (e & 31) * 4;
            float4 v = *(const float4*)(W + row * 128 + col);
            int kk   = row >> 3;
            int rin  = row & 7;
            int tgp  = rin & 3;
            int half = rin >> 2;
            float vv[4] = {v.x, v.y, v.z, v.w};
            #pragma unroll
            for (int d = 0; d < 4; d++) {
                int cc = col + d;
                int j = cc >> 3, gg = cc & 7;
                int jp = j >> 1;
                int c  = (j & 1) * 2 + half;
                int lf = gg * 4 + tgp;
                Wf[(kk * 8 + jp) * LDW + lf * 4 + c] = f2tf32(vv[d]);
            }
        }
    }
    __syncthreads();  // s_idx ready (Wf also in flight; barrier below covers)

    // ---- stage gathered A rows (coalesced per row; one row per warp-iter) ----
    {
        #pragma unroll
        for (int i = 0; i < 32; i++) {
            int v4 = t + i * 256;         // 8192 float4
            int row = v4 >> 5;
            int kq  = (v4 & 31) * 4;
            float4 x = *(const float4*)(table + (long)s_idx[row] * DIN + kq);
            unsigned* dst = As + row * LDA + kq;
            dst[0] = f2tf32(x.x); dst[1] = f2tf32(x.y);
            dst[2] = f2tf32(x.z); dst[3] = f2tf32(x.w);
        }
    }
    __syncthreads();

    // ---- mainloop: warp computes rows [wr0, wr0+32) x all 128 cols ----
    const int wr0 = warp * 32;
    float acc[2][16][4];
    #pragma unroll
    for (int mt = 0; mt < 2; mt++)
        #pragma unroll
        for (int j = 0; j < 16; j++)
            #pragma unroll
            for (int q = 0; q < 4; q++) acc[mt][j][q] = 0.f;

    #pragma unroll 4
    for (int kk = 0; kk < 16; kk++) {
        unsigned a[2][4];
        #pragma unroll
        for (int mt = 0; mt < 2; mt++) {
            const unsigned* ab = As + (wr0 + mt * 16) * LDA + kk * 8;
            a[mt][0] = ab[g * LDA + tg];
            a[mt][1] = ab[(g + 8) * LDA + tg];
            a[mt][2] = ab[g * LDA + tg + 4];
            a[mt][3] = ab[(g + 8) * LDA + tg + 4];
        }
        const unsigned* wb = Wf + kk * 8 * LDW + lane * 4;
        #pragma unroll
        for (int jp = 0; jp < 8; jp++) {
            uint4 bv = *(const uint4*)(wb + jp * LDW);
            mma_tf32(acc[0][2 * jp],     a[0], bv.x, bv.y);
            mma_tf32(acc[0][2 * jp + 1], a[0], bv.z, bv.w);
            mma_tf32(acc[1][2 * jp],     a[1], bv.x, bv.y);
            mma_tf32(acc[1][2 * jp + 1], a[1], bv.z, bv.w);
        }
    }

    // ---- epilogue ----
    #pragma unroll
    for (int mt = 0; mt < 2; mt++) {
        int rbase = row0 + wr0 + mt * 16;
        #pragma unroll
        for (int j = 0; j < 16; j++) {
            int c = col0 + j * 8 + 2 * tg;
            int r0g = rbase + g;
            if (r0g < M)
                *(float2*)(out + (long)r0g * ldout + c) =
                    make_float2(acc[mt][j][0], acc[mt][j][1]);
            int r1g = rbase + 8 + g;
            if (r1g < M)
                *(float2*)(out + (long)r1g * ldout + c) =
                    make_float2(acc[mt][j][2], acc[mt][j][3]);
        }
    }
}

// ---------------------------------------------------------------------------
// Finalize: dedup via match_any, batched 14-way reduction (2 barriers total).
// One block (128 threads) per node.
// ---------------------------------------------------------------------------
#define NRED 14
__global__ __launch_bounds__(128) void finalize_kernel(
    const int* __restrict__ layer_idx, const int* __restrict__ col_idx,
    const float* __restrict__ mu_w, float* __restrict__ out)
{
    const int b = blockIdx.x;
    const int t = threadIdx.x;
    const int lane = t & 31;
    const int warp = t >> 5;

    __shared__ int   s_col[EPB], s_vm[EPB];
    __shared__ float s_cnt[NMC];
    __shared__ float s_red[4][NRED];

    if (warp == 0) {
        int lay = layer_idx[b * EPB + lane];
        int col = col_idx[b * EPB + lane];
        int key = lay * 32768 + col;
        unsigned mm = __match_any_sync(0xffffffffu, key);
        bool valid = ((mm & ((1u << lane) - 1u)) == 0u);  // first occurrence
        s_col[lane] = col;
        s_vm[lane] = valid ? lay : -1;
        unsigned c0 = __ballot_sync(0xffffffffu, valid && lay == 0);
        unsigned c1 = __ballot_sync(0xffffffffu, valid && lay == 1);
        unsigned c2 = __ballot_sync(0xffffffffu, valid && lay == 2);
        unsigned c3 = __ballot_sync(0xffffffffu, valid && lay == 3);
        if (lane == 0) {
            s_cnt[0] = (float)__popc(c0); s_cnt[1] = (float)__popc(c1);
            s_cnt[2] = (float)__popc(c2); s_cnt[3] = (float)__popc(c3);
        }
    }
    __syncthreads();

    // gather (uniform branches; loads independent -> high MLP)
    float nb[NMC] = {0.f, 0.f, 0.f, 0.f};
    #pragma unroll
    for (int e = 0; e < EPB; e++) {
        int m = s_vm[e];
        if (m >= 0) {
            float v = g_embed_v[(long)s_col[e] * DOUT + t];
            if      (m == 0) nb[0] += v;
            else if (m == 1) nb[1] += v;
            else if (m == 2) nb[2] += v;
            else             nb[3] += v;
        }
    }
    #pragma unroll
    for (int m = 0; m < NMC; m++)
        nb[m] = (s_cnt[m] > 0.f) ? nb[m] / s_cnt[m] : 0.f;

    const float* ar = g_agg_all + (long)b * (3 * DOUT);
    const float* fr = g_ff_all  + (long)b * (3 * DOUT);
    float sa  = ar[t], k0 = ar[DOUT + t], q0 = ar[2 * DOUT + t];
    float sff = fr[t], k1 = fr[DOUT + t], q1 = fr[2 * DOUT + t];
    float mu0 = mu_w[t], mu1 = mu_w[DOUT + t];

    // batched reductions
    float p[NRED];
    p[0] = sa * sa;   p[1] = sa * mu0;
    p[2] = nb[0] * nb[0]; p[3] = nb[0] * mu1;
    p[4] = nb[1] * nb[1]; p[5] = nb[1] * mu1;
    p[6] = nb[2] * nb[2]; p[7] = nb[2] * mu1;
    p[8] = nb[3] * nb[3]; p[9] = nb[3] * mu1;
    p[10] = k0 * q0; p[11] = k0 * q1; p[12] = k1 * q0; p[13] = k1 * q1;

    #pragma unroll
    for (int o = 16; o > 0; o >>= 1)
        #pragma unroll
        for (int i = 0; i < NRED; i++)
            p[i] += __shfl_xor_sync(0xffffffffu, p[i], o);
    if (lane < NRED) s_red[warp][lane] = p[lane];
    __syncthreads();
    float r[NRED];
    #pragma unroll
    for (int i = 0; i < NRED; i++)
        r[i] = s_red[0][i] + s_red[1][i] + s_red[2][i] + s_red[3][i];

    // persona softmax
    float logit[NMC];
    #pragma unroll
    for (int m = 0; m < NMC; m++)
        logit[m] = (r[1] + r[3 + 2 * m]) / fmaxf(sqrtf(r[0] + r[2 + 2 * m]), 1e-12f);
    float mx = fmaxf(fmaxf(logit[0], logit[1]), fmaxf(logit[2], logit[3]));
    float ex[NMC], es = 0.f;
    #pragma unroll
    for (int m = 0; m < NMC; m++) { ex[m] = expf(logit[m] - mx); es += ex[m]; }
    float nsum = 0.f;
    #pragma unroll
    for (int m = 0; m < NMC; m++) nsum += (ex[m] / es) * nb[m];

    float va = 0.5f * (sa + nsum);

    // 2x2 highway attention
    float s00 = r[10] * (1.f / 128.f), s01 = r[11] * (1.f / 128.f);
    float s10 = r[12] * (1.f / 128.f), s11 = r[13] * (1.f / 128.f);
    float m0 = fmaxf(s00, s01), m1 = fmaxf(s10, s11);
    float e00 = expf(s00 - m0), e01 = expf(s01 - m0);
    float e10 = expf(s10 - m1), e11 = expf(s11 - m1);
    float new0 = (e00 * va + e01 * sff) / (e00 + e01);
    float new1 = (e10 * va + e11 * sff) / (e10 + e11);

    float o0 = RES * va  + (1.f - RES) * new0;
    float o1 = RES * sff + (1.f - RES) * new1;
    o0 = (o0 > 0.f) ? o0 : expm1f(o0);
    o1 = (o1 > 0.f) ? o1 : expm1f(o1);

    out[(long)b * DOUT + t]             = o0;
    out[(long)NB * DOUT + (long)b * DOUT + t] = o1;
}

// ---------------------------------------------------------------------------
extern "C" void kernel_launch(void* const* d_in, const int* in_sizes, int n_in,
                              void* d_out, int out_size)
{
    const int*   nodes      = (const int*)  d_in[0];
    const int*   unique_ids = (const int*)  d_in[1];
    // d_in[2] = row_idx: repeat(arange(B), 32) — implicit
    const int*   layer_idx  = (const int*)  d_in[3];
    const int*   col_idx    = (const int*)  d_in[4];
    const float* agg_table  = (const float*)d_in[5];
    const float* ff_table   = (const float*)d_in[6];
    const float* Wv_agg     = (const float*)d_in[7];
    const float* Wv_ff      = (const float*)d_in[8];
    const float* Wk         = (const float*)d_in[9];
    const float* Wq         = (const float*)d_in[10];
    const float* mu_w       = (const float*)d_in[11];
    float* out = (float*)d_out;

    float *embed_v, *agg_all, *ff_all;
    cudaGetSymbolAddress((void**)&embed_v, g_embed_v);
    cudaGetSymbolAddress((void**)&agg_all, g_agg_all);
    cudaGetSymbolAddress((void**)&ff_all,  g_ff_all);

    const int smem_bytes = (256 * LDA + 16 * 8 * LDW) * (int)sizeof(unsigned); // 202752
    static int configured = 0;
    cudaFuncSetAttribute(gemm_tc_kernel,
                         cudaFuncAttributeMaxDynamicSharedMemorySize, smem_bytes);
    (void)configured;

    gemm_tc_kernel<<<NB3 + 48, 256, smem_bytes>>>(
        agg_table, ff_table, unique_ids, nodes,
        Wv_agg, Wv_ff, Wk, Wq, embed_v, agg_all, ff_all);

    finalize_kernel<<<NB, 128>>>(layer_idx, col_idx, mu_w, out);
}

// round 3
// speedup vs baseline: 3.4750x; 1.6222x over previous
#include <cuda_runtime.h>
#include <math.h>

#define DIN   128
#define DOUT  128
#define NB    2048
#define NU    20000
#define NMC   4
#define EPB   32
#define RES   0.9f

#define NBE   79            // ceil(20000/256) blocks for embed GEMM
#define LDA   132           // A smem row stride (words): banks (4g+tg)%32 distinct
#define LDWS  132           // W smem row stride (words)

// Scratch
__device__ float g_embed_v[NU * DOUT];        // [20000,128]
__device__ float g_agg_all[NB * 3 * DOUT];    // [2048,384] = self_agg | K0 | Q0
__device__ float g_ff_all [NB * 3 * DOUT];    // [2048,384] = self_ff  | K1 | Q1

__device__ __forceinline__ unsigned f2tf32(float f) {
    unsigned u;
    asm("cvt.rna.tf32.f32 %0, %1;" : "=r"(u) : "f"(f));
    return u;
}

__device__ __forceinline__ void mma_tf32(float* c, const unsigned* a,
                                         unsigned b0, unsigned b1) {
    asm volatile(
        "mma.sync.aligned.m16n8k8.row.col.f32.tf32.tf32.f32 "
        "{%0,%1,%2,%3}, {%4,%5,%6,%7}, {%8,%9}, {%0,%1,%2,%3};\n"
        : "+f"(c[0]), "+f"(c[1]), "+f"(c[2]), "+f"(c[3])
        : "r"(a[0]), "r"(a[1]), "r"(a[2]), "r"(a[3]), "r"(b0), "r"(b1));
}

// ---------------------------------------------------------------------------
// Merged gather-GEMM (tf32). Block: m256 x n128, K=128. 256 thr = 8 warps.
// A raw fp32 bits (HW tf32 truncation). W cvt.rna, row-major in smem.
// ---------------------------------------------------------------------------
__global__ __launch_bounds__(256, 1) void gemm_tc_kernel(
    const float* __restrict__ agg_table, const float* __restrict__ ff_table,
    const int* __restrict__ unique_ids,  const int* __restrict__ nodes,
    const float* __restrict__ Wv_agg, const float* __restrict__ Wv_ff,
    const float* __restrict__ Wk,     const float* __restrict__ Wq)
{
    extern __shared__ unsigned smem[];
    unsigned* As = smem;                    // [256][LDA]
    unsigned* Ws = smem + 256 * LDA;        // [128][LDWS]

    // job decode
    const float* table; const int* idx; const float* W; float* out;
    int M, ldout, col0, row0;
    int bx = blockIdx.x;
    if (bx < NBE) {
        table = agg_table; idx = unique_ids; W = Wv_agg; out = g_embed_v;
        M = NU; ldout = DOUT; col0 = 0; row0 = bx * 256;
    } else {
        int b = bx - NBE;
        int grp = b / 24;            // 0: agg, 1: ff
        int b2 = b % 24;
        int wsel = b2 / 8, mb = b2 % 8;
        table = grp ? ff_table : agg_table;
        idx = nodes;
        W = (wsel == 0) ? (grp ? Wv_ff : Wv_agg) : (wsel == 1 ? Wk : Wq);
        out = grp ? g_ff_all : g_agg_all;
        M = NB; ldout = 3 * DOUT; col0 = wsel * 128; row0 = mb * 256;
    }

    const int t = threadIdx.x;
    const int lane = t & 31;
    const int warp = t >> 5;
    const int g  = lane >> 2;
    const int tg = lane & 3;

    // stage W: row-major, coalesced float4 loads, cvt.rna, STS.128
    #pragma unroll
    for (int i = 0; i < 16; i++) {
        int row = warp + i * 8;             // (t + i*256) >> 5
        float4 v = *(const float4*)(W + row * 128 + lane * 4);
        unsigned* dst = Ws + row * LDWS + lane * 4;
        unsigned u0 = f2tf32(v.x), u1 = f2tf32(v.y);
        unsigned u2 = f2tf32(v.z), u3 = f2tf32(v.w);
        *(uint4*)dst = make_uint4(u0, u1, u2, u3);
    }

    // stage A: per-warp row w+8i; uniform idx LDG -> LDG.128 -> STS.128 (raw)
    #pragma unroll
    for (int i = 0; i < 32; i++) {
        int row = warp + i * 8;
        int gr = row0 + row;
        gr = (gr < M) ? gr : (M - 1);
        int ridx = __ldg(idx + gr);
        float4 x = *(const float4*)(table + (long)ridx * DIN + lane * 4);
        *(float4*)(As + row * LDA + lane * 4) = x;
    }
    __syncthreads();

    // mainloop: warp computes rows [warp*32, +32) x 128 cols
    const int wr0 = warp * 32;
    float acc[2][16][4];
    #pragma unroll
    for (int mt = 0; mt < 2; mt++)
        #pragma unroll
        for (int j = 0; j < 16; j++)
            #pragma unroll
            for (int q = 0; q < 4; q++) acc[mt][j][q] = 0.f;

    #pragma unroll 4
    for (int kk = 0; kk < 16; kk++) {
        unsigned a[2][4];
        #pragma unroll
        for (int mt = 0; mt < 2; mt++) {
            const unsigned* ab = As + (wr0 + mt * 16) * LDA + kk * 8;
            a[mt][0] = ab[g * LDA + tg];
            a[mt][1] = ab[(g + 8) * LDA + tg];
            a[mt][2] = ab[g * LDA + tg + 4];
            a[mt][3] = ab[(g + 8) * LDA + tg + 4];
        }
        const unsigned* wrow0 = Ws + (kk * 8 + tg) * LDWS + g;
        const unsigned* wrow1 = Ws + (kk * 8 + tg + 4) * LDWS + g;
        #pragma unroll
        for (int jp = 0; jp < 8; jp++) {
            unsigned b00 = wrow0[jp * 16];
            unsigned b10 = wrow1[jp * 16];
            unsigned b01 = wrow0[jp * 16 + 8];
            unsigned b11 = wrow1[jp * 16 + 8];
            mma_tf32(acc[0][2 * jp],     a[0], b00, b10);
            mma_tf32(acc[0][2 * jp + 1], a[0], b01, b11);
            mma_tf32(acc[1][2 * jp],     a[1], b00, b10);
            mma_tf32(acc[1][2 * jp + 1], a[1], b01, b11);
        }
    }

    // epilogue
    #pragma unroll
    for (int mt = 0; mt < 2; mt++) {
        int rbase = row0 + wr0 + mt * 16;
        #pragma unroll
        for (int j = 0; j < 16; j++) {
            int c = col0 + j * 8 + 2 * tg;
            int r0g = rbase + g;
            if (r0g < M)
                *(float2*)(out + (long)r0g * ldout + c) =
                    make_float2(acc[mt][j][0], acc[mt][j][1]);
            int r1g = rbase + 8 + g;
            if (r1g < M)
                *(float2*)(out + (long)r1g * ldout + c) =
                    make_float2(acc[mt][j][2], acc[mt][j][3]);
        }
    }
}

// ---------------------------------------------------------------------------
// Finalize: warp-per-node, lane owns 4 dims (float4). No smem, no barriers.
// ---------------------------------------------------------------------------
#define NRED 14
__global__ __launch_bounds__(128) void finalize_kernel(
    const int* __restrict__ layer_idx, const int* __restrict__ col_idx,
    const float* __restrict__ mu_w, float* __restrict__ out)
{
    const int lane = threadIdx.x & 31;
    const int warp = threadIdx.x >> 5;
    const int n = blockIdx.x * 4 + warp;

    // dedup (set semantics): first occurrence of (lay,col) within the warp
    int lay = layer_idx[n * EPB + lane];
    int col = col_idx[n * EPB + lane];
    int key = (lay << 15) | col;                 // col < 20000 < 2^15
    unsigned mm = __match_any_sync(0xffffffffu, key);
    bool valid = ((mm & ((1u << lane) - 1u)) == 0u);
    int vm = valid ? lay : -1;
    float cnt[NMC];
    cnt[0] = (float)__popc(__ballot_sync(0xffffffffu, valid && lay == 0));
    cnt[1] = (float)__popc(__ballot_sync(0xffffffffu, valid && lay == 1));
    cnt[2] = (float)__popc(__ballot_sync(0xffffffffu, valid && lay == 2));
    cnt[3] = (float)__popc(__ballot_sync(0xffffffffu, valid && lay == 3));

    // gather: 32 unconditional coalesced LDG.128, branchless selector FMA
    float4 nb[NMC];
    #pragma unroll
    for (int m = 0; m < NMC; m++) nb[m] = make_float4(0.f, 0.f, 0.f, 0.f);

    #pragma unroll
    for (int e = 0; e < EPB; e++) {
        int me = __shfl_sync(0xffffffffu, vm,  e);
        int ce = __shfl_sync(0xffffffffu, col, e);
        float4 v = *(const float4*)(g_embed_v + (long)ce * DOUT + lane * 4);
        #pragma unroll
        for (int m = 0; m < NMC; m++) {
            float w = (me == m) ? 1.f : 0.f;
            nb[m].x += v.x * w; nb[m].y += v.y * w;
            nb[m].z += v.z * w; nb[m].w += v.w * w;
        }
    }
    #pragma unroll
    for (int m = 0; m < NMC; m++) {
        float inv = 1.f / fmaxf(cnt[m], 1.f);
        nb[m].x *= inv; nb[m].y *= inv; nb[m].z *= inv; nb[m].w *= inv;
    }

    // per-lane dims [4*lane, 4*lane+4)
    const float* ar = g_agg_all + (long)n * (3 * DOUT);
    const float* fr = g_ff_all  + (long)n * (3 * DOUT);
    float4 sa  = *(const float4*)(ar + lane * 4);
    float4 k0  = *(const float4*)(ar + DOUT + lane * 4);
    float4 q0  = *(const float4*)(ar + 2 * DOUT + lane * 4);
    float4 sff = *(const float4*)(fr + lane * 4);
    float4 k1  = *(const float4*)(fr + DOUT + lane * 4);
    float4 q1  = *(const float4*)(fr + 2 * DOUT + lane * 4);
    float4 mu0 = *(const float4*)(mu_w + lane * 4);
    float4 mu1 = *(const float4*)(mu_w + DOUT + lane * 4);

    #define DOT4(a, b) ((a).x*(b).x + (a).y*(b).y + (a).z*(b).z + (a).w*(b).w)
    float p[NRED];
    p[0]  = DOT4(sa, sa);      p[1]  = DOT4(sa, mu0);
    p[2]  = DOT4(nb[0], nb[0]); p[3] = DOT4(nb[0], mu1);
    p[4]  = DOT4(nb[1], nb[1]); p[5] = DOT4(nb[1], mu1);
    p[6]  = DOT4(nb[2], nb[2]); p[7] = DOT4(nb[2], mu1);
    p[8]  = DOT4(nb[3], nb[3]); p[9] = DOT4(nb[3], mu1);
    p[10] = DOT4(k0, q0); p[11] = DOT4(k0, q1);
    p[12] = DOT4(k1, q0); p[13] = DOT4(k1, q1);

    #pragma unroll
    for (int o = 16; o > 0; o >>= 1)
        #pragma unroll
        for (int i = 0; i < NRED; i++)
            p[i] += __shfl_xor_sync(0xffffffffu, p[i], o);

    // persona softmax
    float logit[NMC];
    #pragma unroll
    for (int m = 0; m < NMC; m++)
        logit[m] = (p[1] + p[3 + 2 * m]) / fmaxf(sqrtf(p[0] + p[2 + 2 * m]), 1e-12f);
    float mx = fmaxf(fmaxf(logit[0], logit[1]), fmaxf(logit[2], logit[3]));
    float ex[NMC], es = 0.f;
    #pragma unroll
    for (int m = 0; m < NMC; m++) { ex[m] = expf(logit[m] - mx); es += ex[m]; }
    float4 nsum = make_float4(0.f, 0.f, 0.f, 0.f);
    #pragma unroll
    for (int m = 0; m < NMC; m++) {
        float c = ex[m] / es;
        nsum.x += c * nb[m].x; nsum.y += c * nb[m].y;
        nsum.z += c * nb[m].z; nsum.w += c * nb[m].w;
    }
    float4 va = make_float4(0.5f * (sa.x + nsum.x), 0.5f * (sa.y + nsum.y),
                            0.5f * (sa.z + nsum.z), 0.5f * (sa.w + nsum.w));

    // 2x2 highway attention
    float s00 = p[10] * (1.f / 128.f), s01 = p[11] * (1.f / 128.f);
    float s10 = p[12] * (1.f / 128.f), s11 = p[13] * (1.f / 128.f);
    float m0 = fmaxf(s00, s01), m1 = fmaxf(s10, s11);
    float e00 = expf(s00 - m0), e01 = expf(s01 - m0);
    float e10 = expf(s10 - m1), e11 = expf(s11 - m1);
    float w00 = e00 / (e00 + e01), w01 = e01 / (e00 + e01);
    float w10 = e10 / (e10 + e11), w11 = e11 / (e10 + e11);

    float4 o0, o1;
    #define FIN(comp) do { \
        float nv0 = w00 * va.comp + w01 * sff.comp; \
        float nv1 = w10 * va.comp + w11 * sff.comp; \
        float a0 = RES * va.comp  + (1.f - RES) * nv0; \
        float a1 = RES * sff.comp + (1.f - RES) * nv1; \
        o0.comp = (a0 > 0.f) ? a0 : expm1f(a0); \
        o1.comp = (a1 > 0.f) ? a1 : expm1f(a1); \
    } while (0)
    FIN(x); FIN(y); FIN(z); FIN(w);

    *(float4*)(out + (long)n * DOUT + lane * 4) = o0;
    *(float4*)(out + (long)NB * DOUT + (long)n * DOUT + lane * 4) = o1;
}

// ---------------------------------------------------------------------------
extern "C" void kernel_launch(void* const* d_in, const int* in_sizes, int n_in,
                              void* d_out, int out_size)
{
    const int*   nodes      = (const int*)  d_in[0];
    const int*   unique_ids = (const int*)  d_in[1];
    // d_in[2] = row_idx: repeat(arange(B), 32) — implicit
    const int*   layer_idx  = (const int*)  d_in[3];
    const int*   col_idx    = (const int*)  d_in[4];
    const float* agg_table  = (const float*)d_in[5];
    const float* ff_table   = (const float*)d_in[6];
    const float* Wv_agg     = (const float*)d_in[7];
    const float* Wv_ff      = (const float*)d_in[8];
    const float* Wk         = (const float*)d_in[9];
    const float* Wq         = (const float*)d_in[10];
    const float* mu_w       = (const float*)d_in[11];
    float* out = (float*)d_out;

    const int smem_bytes = (256 * LDA + 128 * LDWS) * (int)sizeof(unsigned);
    cudaFuncSetAttribute(gemm_tc_kernel,
                         cudaFuncAttributeMaxDynamicSharedMemorySize, smem_bytes);

    gemm_tc_kernel<<<NBE + 48, 256, smem_bytes>>>(
        agg_table, ff_table, unique_ids, nodes, Wv_agg, Wv_ff, Wk, Wq);

    finalize_kernel<<<NB / 4, 128>>>(layer_idx, col_idx, mu_w, out);
}